// round 17
// baseline (speedup 1.0000x reference)
#include <cuda_runtime.h>
#include <cuda_fp16.h>
#include <cstdint>
#include <math.h>

#define NN 100000

// ---------------- scratch ----------------
__device__ __half g_Xh [(size_t)NN * 128];
__device__ __half g_Qh [(size_t)NN * 128];
__device__ __half g_Vh [(size_t)5 * NN * 128];
__device__ float  g_E  [(size_t)NN * 20];
__device__ __half g_Hth[(size_t)NN * 128];     // fp16 H (residual for FFN2)
__device__ __half g_Fh [(size_t)NN * 512];
__device__ __half g_WQh [128 * 128];
__device__ __half g_WKVh[5 * 256 * 128];   // [r][c(K:0-127,V:128-255)][k]
__device__ __half g_W1h [512 * 128];
__device__ __half g_W2h [128 * 512];
__device__ float  g_denom[20];

__device__ __forceinline__ uint32_t smem_u32(const void* p) {
    uint32_t a;
    asm("{ .reg .u64 t; cvta.to.shared.u64 t, %1; cvt.u32.u64 %0, t; }" : "=r"(a) : "l"(p));
    return a;
}
__device__ __forceinline__ void cpa16(uint32_t dst, const void* src) {
    asm volatile("cp.async.ca.shared.global [%0], [%1], 16;" :: "r"(dst), "l"(src));
}

// merged: x conversion + denom zero + all weight transposes
__global__ void prep_kernel(const float* __restrict__ x,
                            const float* __restrict__ wk, const float* __restrict__ wv,
                            const float* __restrict__ wq, const float* __restrict__ W1,
                            const float* __restrict__ W2) {
    int tid = threadIdx.x;
    if (blockIdx.x < 12500) {
        if (blockIdx.x == 0 && tid < 20) g_denom[tid] = 0.0f;
        size_t i = ((size_t)blockIdx.x * 256 + tid) * 4;
        if (i >= (size_t)NN * 128) return;
        float4 v = *(const float4*)(x + i);
        *(__half2*)(g_Xh + i)     = __floats2half2_rn(v.x, v.y);
        *(__half2*)(g_Xh + i + 2) = __floats2half2_rn(v.z, v.w);
        return;
    }
    int b = blockIdx.x - 12500;
    if (b < 640) {
        int z = b >> 7;
        int idx = (b & 127) * 256 + tid;
        int c = idx >> 7, k = idx & 127;
        float v;
        if (c < 128) {
            v = wk[(size_t)(c >> 5) * 20480 + (size_t)z * 4096 + k * 32 + (c & 31)];
        } else {
            int c2 = c - 128;
            v = wv[(size_t)(c2 >> 5) * 20480 + (size_t)z * 4096 + k * 32 + (c2 & 31)];
        }
        g_WKVh[(size_t)z * 32768 + idx] = __float2half_rn(v);
    } else {
        int b2 = b - 640;
        if (b2 < 64) {
            int idx = b2 * 256 + tid;
            int c = idx >> 7, k = idx & 127;
            g_WQh[idx] = __float2half_rn(wq[(size_t)(c >> 5) * 4096 + k * 32 + (c & 31)]);
        } else if (b2 < 320) {
            int idx = (b2 - 64) * 256 + tid;
            int c = idx >> 7, k = idx & 127;
            g_W1h[idx] = __float2half_rn(W1[(size_t)k * 512 + c]);
        } else {
            int idx = (b2 - 320) * 256 + tid;
            int c = idx >> 9, k = idx & 511;
            g_W2h[idx] = __float2half_rn(W2[(size_t)k * 128 + c]);
        }
    }
}

#define LDM_X4(r0,r1,r2,r3,addr) \
    asm volatile("ldmatrix.sync.aligned.m8n8.x4.shared.b16 {%0,%1,%2,%3}, [%4];" \
                 : "=r"(r0), "=r"(r1), "=r"(r2), "=r"(r3) : "r"(addr))
#define MMA_F16(dd,aa,bb) \
    asm volatile("mma.sync.aligned.m16n8k16.row.col.f32.f16.f16.f32 " \
                 "{%0,%1,%2,%3}, {%4,%5,%6,%7}, {%8,%9}, {%0,%1,%2,%3};" \
                 : "+f"((dd)[0]), "+f"((dd)[1]), "+f"((dd)[2]), "+f"((dd)[3]) \
                 : "r"((aa)[0]), "r"((aa)[1]), "r"((aa)[2]), "r"((aa)[3]), \
                   "r"((bb)[0]), "r"((bb)[1]))

__device__ __forceinline__ void chunk_mma(uint32_t abase, uint32_t bbase,
                                          int m0w, int n0w, int lane,
                                          float d[2][8][4]) {
    const int lrow = lane & 7;
    const int a_hi = (lane >> 3) >> 1, a_roff = ((lane >> 3) & 1) * 8;
    const int b_hi = (lane >> 3) & 1,  b_coff = (lane >> 4) * 8;
#pragma unroll
    for (int ks = 0; ks < 4; ++ks) {
        uint32_t a[2][4], b[8][2];
#pragma unroll
        for (int mf = 0; mf < 2; ++mf) {
            int r = m0w + mf * 16 + lrow + a_roff;
            uint32_t addr = abase + (uint32_t)r * 128u
                          + (uint32_t)(((2 * ks + a_hi) ^ lrow) << 4);
            LDM_X4(a[mf][0], a[mf][1], a[mf][2], a[mf][3], addr);
        }
#pragma unroll
        for (int pr = 0; pr < 4; ++pr) {
            int c = n0w + pr * 16 + lrow + b_coff;
            uint32_t addr = bbase + (uint32_t)c * 128u
                          + (uint32_t)(((2 * ks + b_hi) ^ (c & 7)) << 4);
            LDM_X4(b[2*pr][0], b[2*pr][1], b[2*pr+1][0], b[2*pr+1][1], addr);
        }
#pragma unroll
        for (int mf = 0; mf < 2; ++mf)
#pragma unroll
            for (int nf = 0; nf < 8; ++nf) MMA_F16(d[mf][nf], a[mf], b[nf]);
    }
}

#define ZERO_D(d) \
    { _Pragma("unroll") for (int i = 0; i < 2; i++) \
      _Pragma("unroll") for (int j = 0; j < 8; j++) \
      _Pragma("unroll") for (int q = 0; q < 4; q++) (d)[i][j][q] = 0.0f; }

__device__ __forceinline__ void stage_h16(char* sCh, int m0w, int n0w, int lane,
                                          float d[2][8][4],
                                          int epi, const float* bias, int cg0) {
    const int g4 = lane >> 2, t4 = lane & 3;
#pragma unroll
    for (int mf = 0; mf < 2; ++mf)
#pragma unroll
        for (int nf = 0; nf < 8; ++nf) {
            int col = n0w + nf * 8 + t4 * 2;
            float b0 = 0.f, b1 = 0.f;
            if (epi == 1) { b0 = bias[cg0 + col]; b1 = bias[cg0 + col + 1]; }
#pragma unroll
            for (int rh = 0; rh < 2; ++rh) {
                int row = m0w + mf * 16 + g4 + rh * 8;
                float v0 = d[mf][nf][2*rh], v1 = d[mf][nf][2*rh+1];
                if (epi == 1) {
                    v0 = fmaxf(v0 + b0, 0.f);
                    v1 = fmaxf(v1 + b1, 0.f);
                }
                *(__half2*)(sCh + row * 272 + col * 2) = __floats2half2_rn(v0, v1);
            }
        }
}

// ---------------- agemm: A-resident GEMM (K=128), ny col-groups --------------
__global__ __launch_bounds__(256, 2)
void agemm(const __half* __restrict__ A,
           const __half* __restrict__ BT,
           int ny,
           __half* __restrict__ Ch, int Cstride,
           int epi, const float* __restrict__ bias)
{
    extern __shared__ uint32_t sm[];
    char* smc = (char*)sm;
    const uint32_t sbase = smem_u32(smc);
    char* sCh = smc + 65536;

    const int tid  = threadIdx.x;
    const int wid  = tid >> 5;
    const int lane = tid & 31;
    const int m0   = blockIdx.x * 128;
    const int m0w  = (wid >> 1) * 32;
    const int n0w  = (wid & 1) * 64;
    const int srow = tid >> 3, schk = tid & 7;

#pragma unroll
    for (int ch = 0; ch < 2; ++ch) {
#pragma unroll
        for (int p = 0; p < 4; ++p) {
            int row = srow + p * 32;
            int ar  = m0 + row; if (ar >= NN) ar = NN - 1;
            uint32_t off = (uint32_t)row * 128u + (uint32_t)((schk ^ (row & 7)) << 4);
            cpa16(sbase + ch * 16384u + off, A + (size_t)ar * 128 + ch * 64 + schk * 8);
        }
        asm volatile("cp.async.commit_group;" ::: "memory");
    }
#pragma unroll
    for (int ch = 0; ch < 2; ++ch) {
#pragma unroll
        for (int p = 0; p < 4; ++p) {
            int row = srow + p * 32;
            uint32_t off = (uint32_t)row * 128u + (uint32_t)((schk ^ (row & 7)) << 4);
            cpa16(sbase + 32768u + ch * 16384u + off,
                  BT + (size_t)row * 128 + ch * 64 + schk * 8);
        }
        asm volatile("cp.async.commit_group;" ::: "memory");
    }

    for (int cy = 0; cy < ny; ++cy) {
        const int cg0 = cy * 128;
        float d[2][8][4];
        ZERO_D(d);
        asm volatile("cp.async.wait_group 1;" ::: "memory");
        __syncthreads();
        chunk_mma(sbase, sbase + 32768u, m0w, n0w, lane, d);
        asm volatile("cp.async.wait_group 0;" ::: "memory");
        __syncthreads();
        chunk_mma(sbase + 16384u, sbase + 49152u, m0w, n0w, lane, d);
        __syncthreads();

        if (cy + 1 < ny) {
            const int cgn = (cy + 1) * 128;
#pragma unroll
            for (int ch = 0; ch < 2; ++ch) {
#pragma unroll
                for (int p = 0; p < 4; ++p) {
                    int row = srow + p * 32;
                    uint32_t off = (uint32_t)row * 128u + (uint32_t)((schk ^ (row & 7)) << 4);
                    cpa16(sbase + 32768u + ch * 16384u + off,
                          BT + (size_t)(cgn + row) * 128 + ch * 64 + schk * 8);
                }
                asm volatile("cp.async.commit_group;" ::: "memory");
            }
        }

        stage_h16(sCh, m0w, n0w, lane, d, epi, bias, cg0);
        __syncthreads();

#pragma unroll
        for (int p = 0; p < 8; ++p) {
            int i   = tid + p * 256;
            int row = i >> 4;
            int u   = i & 15;
            int gr  = m0 + row;
            if (gr >= NN) continue;
            uint4 v = *(const uint4*)(sCh + row * 272 + u * 16);
            *(uint4*)(Ch + (size_t)gr * Cstride + cg0 + u * 8) = v;
        }
    }
}

// ---------------- cgemm: fused combine+LN1 prologue + FFN1 GEMM --------------
__global__ __launch_bounds__(256, 2)
void cgemm(const float* __restrict__ x,
           const float* __restrict__ g1, const float* __restrict__ be1,
           const __half* __restrict__ BT,
           const float* __restrict__ bias,
           __half* __restrict__ Ch)
{
    extern __shared__ uint32_t sm[];
    char* smc = (char*)sm;
    const uint32_t sbase = smem_u32(smc);
    char* sCh = smc + 65536;
    __shared__ float sinv[20];

    const int tid  = threadIdx.x;
    const int wid  = tid >> 5;
    const int lane = tid & 31;
    const int m0   = blockIdx.x * 128;
    const int m0w  = (wid >> 1) * 32;
    const int n0w  = (wid & 1) * 64;
    const int srow = tid >> 3, schk = tid & 7;

    if (tid < 20) sinv[tid] = 1.0f / g_denom[tid];

    // issue B(0) loads first (overlap with prologue compute)
#pragma unroll
    for (int ch = 0; ch < 2; ++ch) {
#pragma unroll
        for (int p = 0; p < 4; ++p) {
            int row = srow + p * 32;
            uint32_t off = (uint32_t)row * 128u + (uint32_t)((schk ^ (row & 7)) << 4);
            cpa16(sbase + 32768u + ch * 16384u + off,
                  BT + (size_t)row * 128 + ch * 64 + schk * 8);
        }
        asm volatile("cp.async.commit_group;" ::: "memory");
    }
    __syncthreads();   // sinv visible

    // ---- combine + LN1 for rows m0..m0+127 (16 rows per warp) ----
    for (int rr = wid; rr < 128; rr += 8) {
        int gr = m0 + rr;
        int n  = (gr < NN) ? gr : NN - 1;

        float pv = 0.0f;
        if (lane < 20) pv = g_E[(size_t)n * 20 + lane] * sinv[lane];

        float2 t[2];
        float s1 = 0.0f, s2 = 0.0f;
#pragma unroll
        for (int g = 0; g < 2; ++g) {
            int c = g * 64 + 2 * lane;
            int h = c >> 5;
            float2 zz = make_float2(0.f, 0.f);
#pragma unroll
            for (int r = 0; r < 5; ++r) {
                float p = __shfl_sync(0xffffffffu, pv, h * 5 + r);
                float2 vf = __half22float2(
                    *(const __half2*)(g_Vh + ((size_t)r * NN + n) * 128 + c));
                zz.x = fmaf(p, vf.x, zz.x);
                zz.y = fmaf(p, vf.y, zz.y);
            }
            float2 xv = *(const float2*)(x + (size_t)n * 128 + c);
            float2 v = make_float2(xv.x + zz.x, xv.y + zz.y);
            t[g] = v;
            s1 += v.x + v.y;
            s2 = fmaf(v.x, v.x, fmaf(v.y, v.y, s2));
        }
#pragma unroll
        for (int o = 16; o > 0; o >>= 1) {
            s1 += __shfl_xor_sync(0xffffffffu, s1, o);
            s2 += __shfl_xor_sync(0xffffffffu, s2, o);
        }
        float mu  = s1 * (1.0f / 128.0f);
        float var = s2 * (1.0f / 128.0f) - mu * mu;
        float rs  = rsqrtf(var + 1e-5f);
#pragma unroll
        for (int g = 0; g < 2; ++g) {
            int c = g * 64 + 2 * lane;
            float o0 = (t[g].x - mu) * rs * g1[c]     + be1[c];
            float o1 = (t[g].y - mu) * rs * g1[c + 1] + be1[c + 1];
            __half2 hv = __floats2half2_rn(o0, o1);
            // A tile is TWO 16KB regions: k<64 at +0, k>=64 at +16384.
            // chunk-in-region = (c>>3)&7, byte-in-chunk = (c&7)*2
            uint32_t reg = (uint32_t)(c >> 6) * 16384u;
            uint32_t chk = (uint32_t)((c >> 3) & 7);
            uint32_t soff = reg + (uint32_t)rr * 128u
                          + ((chk ^ (uint32_t)(rr & 7)) << 4) + (uint32_t)((c & 7) * 2);
            *(__half2*)(smc + soff) = hv;
            if (gr < NN)
                *(__half2*)(g_Hth + (size_t)gr * 128 + c) = hv;
        }
    }

    for (int cy = 0; cy < 4; ++cy) {
        const int cg0 = cy * 128;
        float d[2][8][4];
        ZERO_D(d);
        asm volatile("cp.async.wait_group 1;" ::: "memory");
        __syncthreads();
        chunk_mma(sbase, sbase + 32768u, m0w, n0w, lane, d);
        asm volatile("cp.async.wait_group 0;" ::: "memory");
        __syncthreads();
        chunk_mma(sbase + 16384u, sbase + 49152u, m0w, n0w, lane, d);
        __syncthreads();

        if (cy + 1 < 4) {
            const int cgn = (cy + 1) * 128;
#pragma unroll
            for (int ch = 0; ch < 2; ++ch) {
#pragma unroll
                for (int p = 0; p < 4; ++p) {
                    int row = srow + p * 32;
                    uint32_t off = (uint32_t)row * 128u + (uint32_t)((schk ^ (row & 7)) << 4);
                    cpa16(sbase + 32768u + ch * 16384u + off,
                          BT + (size_t)(cgn + row) * 128 + ch * 64 + schk * 8);
                }
                asm volatile("cp.async.commit_group;" ::: "memory");
            }
        }

        stage_h16(sCh, m0w, n0w, lane, d, 1, bias, cg0);
        __syncthreads();

#pragma unroll
        for (int p = 0; p < 8; ++p) {
            int i   = tid + p * 256;
            int row = i >> 4;
            int u   = i & 15;
            int gr  = m0 + row;
            if (gr >= NN) continue;
            uint4 v = *(const uint4*)(sCh + row * 272 + u * 16);
            *(uint4*)(Ch + (size_t)gr * 512 + cg0 + u * 8) = v;
        }
    }
}

// ---------------- kv2: fused K+V, smem Q logits, fp16 V staging --------------
__global__ __launch_bounds__(256, 2)
void kv2(const int* __restrict__ nbr)
{
    extern __shared__ uint32_t sm[];
    char* smc = (char*)sm;
    const uint32_t sbase = smem_u32(smc);
    char* sCh = smc + 65536;
    const uint32_t qbase = sbase + 65536u;
    __shared__ int rowg[128];
    __shared__ float sden[20];

    const int tid  = threadIdx.x;
    const int wid  = tid >> 5;
    const int lane = tid & 31;
    const int g4   = lane >> 2, t4 = lane & 3;
    const int z    = blockIdx.z;
    const int m0   = blockIdx.x * 128;
    const int m0w  = (wid >> 1) * 32;
    const int n0w  = (wid & 1) * 64;
    const int srow = tid >> 3, schk = tid & 7;

    if (tid < 128) {
        int gr  = m0 + tid;
        int idx = (gr < NN) ? gr : (NN - 1);
        if (z > 0 && gr < NN) idx = nbr[gr * 4 + (z - 1)];
        rowg[tid] = idx;
    }
    if (tid < 20) sden[tid] = 0.0f;
    __syncthreads();

    const __half* Bz = g_WKVh + (size_t)z * 32768;

#pragma unroll
    for (int ch = 0; ch < 2; ++ch) {
#pragma unroll
        for (int p = 0; p < 4; ++p) {
            int row = srow + p * 32;
            uint32_t off = (uint32_t)row * 128u + (uint32_t)((schk ^ (row & 7)) << 4);
            cpa16(sbase + ch * 16384u + off,
                  g_Xh + (size_t)rowg[row] * 128 + ch * 64 + schk * 8);
        }
        asm volatile("cp.async.commit_group;" ::: "memory");
    }
#pragma unroll
    for (int ch = 0; ch < 2; ++ch) {
#pragma unroll
        for (int p = 0; p < 4; ++p) {
            int row = srow + p * 32;
            uint32_t off = (uint32_t)row * 128u + (uint32_t)((schk ^ (row & 7)) << 4);
            cpa16(sbase + 32768u + ch * 16384u + off,
                  Bz + (size_t)row * 128 + ch * 64 + schk * 8);
        }
        asm volatile("cp.async.commit_group;" ::: "memory");
    }
    {
#pragma unroll
        for (int p = 0; p < 8; ++p) {
            int i   = tid + p * 256;
            int row = i >> 4;
            int u   = i & 15;
            int gr  = m0 + row; if (gr >= NN) gr = NN - 1;
            cpa16(qbase + (uint32_t)row * 272u + (uint32_t)u * 16u,
                  g_Qh + (size_t)gr * 128 + u * 8);
        }
        asm volatile("cp.async.commit_group;" ::: "memory");
    }

    float d[2][8][4];
    ZERO_D(d);
    asm volatile("cp.async.wait_group 2;" ::: "memory");
    __syncthreads();
    chunk_mma(sbase, sbase + 32768u, m0w, n0w, lane, d);
    asm volatile("cp.async.wait_group 1;" ::: "memory");
    __syncthreads();
    chunk_mma(sbase + 16384u, sbase + 49152u, m0w, n0w, lane, d);
    __syncthreads();

#pragma unroll
    for (int ch = 0; ch < 2; ++ch) {
#pragma unroll
        for (int p = 0; p < 4; ++p) {
            int row = srow + p * 32;
            uint32_t off = (uint32_t)row * 128u + (uint32_t)((schk ^ (row & 7)) << 4);
            cpa16(sbase + 32768u + ch * 16384u + off,
                  Bz + (size_t)(128 + row) * 128 + ch * 64 + schk * 8);
        }
        asm volatile("cp.async.commit_group;" ::: "memory");
    }

    asm volatile("cp.async.wait_group 2;" ::: "memory");   // Q done
    __syncthreads();

    {
        const float scale = 0.1767766952966369f;
        const int hbase = n0w >> 5;
        float esum0 = 0.f, esum1 = 0.f;
#pragma unroll
        for (int mf = 0; mf < 2; ++mf)
#pragma unroll
            for (int rh = 0; rh < 2; ++rh) {
                int lrowq = m0w + mf * 16 + g4 + rh * 8;
                int gr = m0 + lrowq;
                bool valid = gr < NN;
#pragma unroll
                for (int hg = 0; hg < 2; ++hg) {
                    float s = 0.f;
#pragma unroll
                    for (int j = 0; j < 4; ++j) {
                        int nf = hg * 4 + j;
                        int col0 = n0w + nf * 8 + t4 * 2;
                        float2 qv = __half22float2(
                            *(const __half2*)(sCh + lrowq * 272 + col0 * 2));
                        s = fmaf(d[mf][nf][2*rh],     qv.x, s);
                        s = fmaf(d[mf][nf][2*rh + 1], qv.y, s);
                    }
                    s += __shfl_xor_sync(0xffffffffu, s, 1);
                    s += __shfl_xor_sync(0xffffffffu, s, 2);
                    if (t4 == 0 && valid) {
                        float e = expf(s * scale);
                        g_E[(size_t)gr * 20 + (hbase + hg) * 5 + z] = e;
                        if (hg == 0) esum0 += e; else esum1 += e;
                    }
                }
            }
        if (t4 == 0) {
            atomicAdd(&sden[(hbase + 0) * 5 + z], esum0);
            atomicAdd(&sden[(hbase + 1) * 5 + z], esum1);
        }
    }
    __syncthreads();
    if (tid < 20 && sden[tid] != 0.0f) atomicAdd(&g_denom[tid], sden[tid]);

    ZERO_D(d);
    asm volatile("cp.async.wait_group 1;" ::: "memory");
    __syncthreads();
    chunk_mma(sbase, sbase + 32768u, m0w, n0w, lane, d);
    asm volatile("cp.async.wait_group 0;" ::: "memory");
    __syncthreads();
    chunk_mma(sbase + 16384u, sbase + 49152u, m0w, n0w, lane, d);
    __syncthreads();

    stage_h16(sCh, m0w, n0w, lane, d, 3, nullptr, 0);
    __syncthreads();
#pragma unroll
    for (int p = 0; p < 8; ++p) {
        int i   = tid + p * 256;
        int row = i >> 4;
        int u   = i & 15;
        int gr  = m0 + row;
        if (gr >= NN) continue;
        uint4 v = *(const uint4*)(sCh + row * 272 + u * 16);
        *(uint4*)(g_Vh + ((size_t)z * NN + gr) * 128 + u * 8) = v;
    }
}

// ---------------- FFN2 GEMM (K=512) + fp16 resid + LN2 ----------------
__global__ __launch_bounds__(256, 2)
void tgemm2(const __half* __restrict__ A,
            const __half* __restrict__ BT,
            float* __restrict__ C,
            const float* __restrict__ bias,
            const __half* __restrict__ resid,
            const float* __restrict__ gamma,
            const float* __restrict__ beta)
{
    extern __shared__ uint32_t sm[];
    char* smc = (char*)sm;
    const uint32_t sbase = smem_u32(smc);

    const int tid  = threadIdx.x;
    const int wid  = tid >> 5;
    const int lane = tid & 31;
    const int m0   = blockIdx.x * 128;
    const int m0w  = (wid >> 1) * 32;
    const int n0w  = (wid & 1) * 64;
    const int srow = tid >> 3, schk = tid & 7;

    float d[2][8][4];
    ZERO_D(d);

    auto stage = [&](int bsel, int kc) {
        const int kg0 = kc * 64;
        uint32_t abase = sbase + (uint32_t)bsel * 16384u;
        uint32_t bbase = sbase + 32768u + (uint32_t)bsel * 16384u;
#pragma unroll
        for (int p = 0; p < 4; ++p) {
            int row = srow + p * 32;
            int ar  = m0 + row; if (ar >= NN) ar = NN - 1;
            uint32_t off = (uint32_t)row * 128u + (uint32_t)((schk ^ (row & 7)) << 4);
            cpa16(abase + off, A + (size_t)ar * 512 + kg0 + schk * 8);
            cpa16(bbase + off, BT + (size_t)row * 512 + kg0 + schk * 8);
        }
        asm volatile("cp.async.commit_group;" ::: "memory");
    };

    stage(0, 0);
    for (int kc = 0; kc < 8; ++kc) {
        const int bsel = kc & 1;
        if (kc + 1 < 8) { stage(bsel ^ 1, kc + 1);
            asm volatile("cp.async.wait_group 1;" ::: "memory");
        } else { asm volatile("cp.async.wait_group 0;" ::: "memory"); }
        __syncthreads();
        chunk_mma(sbase + (uint32_t)bsel * 16384u,
                  sbase + 32768u + (uint32_t)bsel * 16384u, m0w, n0w, lane, d);
        __syncthreads();
    }

    float* sC = (float*)sm;
    const int g4 = lane >> 2, t4 = lane & 3;
#pragma unroll
    for (int mf = 0; mf < 2; ++mf)
#pragma unroll
        for (int nf = 0; nf < 8; ++nf) {
            int row = m0w + mf * 16 + g4;
            int col = n0w + nf * 8 + t4 * 2;
            *(float2*)(sC + row * 132 + col)       = make_float2(d[mf][nf][0], d[mf][nf][1]);
            *(float2*)(sC + (row + 8) * 132 + col) = make_float2(d[mf][nf][2], d[mf][nf][3]);
        }
    __syncthreads();

    for (int rr = wid; rr < 128; rr += 8) {
        int gr = m0 + rr;
        if (gr >= NN) continue;
        const __half* rp = resid + (size_t)gr * 128;
        float v0 = sC[rr * 132 + lane]      + bias[lane]      + __half2float(rp[lane]);
        float v1 = sC[rr * 132 + 32 + lane] + bias[32 + lane] + __half2float(rp[32 + lane]);
        float v2 = sC[rr * 132 + 64 + lane] + bias[64 + lane] + __half2float(rp[64 + lane]);
        float v3 = sC[rr * 132 + 96 + lane] + bias[96 + lane] + __half2float(rp[96 + lane]);
        float s1 = v0 + v1 + v2 + v3;
        float s2 = v0 * v0 + v1 * v1 + v2 * v2 + v3 * v3;
#pragma unroll
        for (int o = 16; o > 0; o >>= 1) {
            s1 += __shfl_xor_sync(0xffffffffu, s1, o);
            s2 += __shfl_xor_sync(0xffffffffu, s2, o);
        }
        float mu  = s1 * (1.0f / 128.0f);
        float var = s2 * (1.0f / 128.0f) - mu * mu;
        float rs  = rsqrtf(var + 1e-5f);
        float* dst = C + (size_t)gr * 128;
        dst[lane]      = (v0 - mu) * rs * gamma[lane]      + beta[lane];
        dst[lane + 32] = (v1 - mu) * rs * gamma[lane + 32] + beta[lane + 32];
        dst[lane + 64] = (v2 - mu) * rs * gamma[lane + 64] + beta[lane + 64];
        dst[lane + 96] = (v3 - mu) * rs * gamma[lane + 96] + beta[lane + 96];
    }
}

// ---------------- launch ----------------
extern "C" void kernel_launch(void* const* d_in, const int* in_sizes, int n_in,
                              void* d_out, int out_size)
{
    const float* x   = (const float*)d_in[0];
    const int*   nbr = (const int*)  d_in[1];
    const float* wq  = (const float*)d_in[2];
    const float* wk  = (const float*)d_in[3];
    const float* wv  = (const float*)d_in[4];
    const float* W1  = (const float*)d_in[5];
    const float* b1  = (const float*)d_in[6];
    const float* W2  = (const float*)d_in[7];
    const float* b2  = (const float*)d_in[8];
    const float* g1  = (const float*)d_in[9];
    const float* be1 = (const float*)d_in[10];
    const float* g2  = (const float*)d_in[11];
    const float* be2 = (const float*)d_in[12];
    float* out = (float*)d_out;

    void *pXh, *pQh, *pHth, *pFh, *pWQ, *pW1, *pW2;
    cudaGetSymbolAddress(&pXh, g_Xh);
    cudaGetSymbolAddress(&pQh, g_Qh);
    cudaGetSymbolAddress(&pHth, g_Hth);
    cudaGetSymbolAddress(&pFh, g_Fh);
    cudaGetSymbolAddress(&pWQ, g_WQh);
    cudaGetSymbolAddress(&pW1, g_W1h);
    cudaGetSymbolAddress(&pW2, g_W2h);

    const size_t SMEM_AG = 65536 + 128 * 272;                   // 100352
    const size_t SMEM_T2 = (size_t)128 * 132 * sizeof(float);   // 67584
    cudaFuncSetAttribute((const void*)agemm,
                         cudaFuncAttributeMaxDynamicSharedMemorySize, (int)SMEM_AG);
    cudaFuncSetAttribute((const void*)cgemm,
                         cudaFuncAttributeMaxDynamicSharedMemorySize, (int)SMEM_AG);
    cudaFuncSetAttribute((const void*)kv2,
                         cudaFuncAttributeMaxDynamicSharedMemorySize, (int)SMEM_AG);
    cudaFuncSetAttribute((const void*)tgemm2,
                         cudaFuncAttributeMaxDynamicSharedMemorySize, (int)SMEM_T2);

    const int GN = (NN + 127) / 128;   // 782

    prep_kernel<<<13716, 256>>>(x, wk, wv, wq, W1, W2);

    agemm<<<GN, 256, SMEM_AG>>>(
        (const __half*)pXh, (const __half*)pWQ, 1,
        (__half*)pQh, 128, 3, nullptr);

    kv2<<<dim3(GN, 1, 5), 256, SMEM_AG>>>(nbr);

    cgemm<<<GN, 256, SMEM_AG>>>(
        x, g1, be1, (const __half*)pW1, b1, (__half*)pFh);

    tgemm2<<<GN, 256, SMEM_T2>>>(
        (const __half*)pFh, (const __half*)pW2,
        out, b2, (const __half*)pHth, g2, be2);
}